// round 15
// baseline (speedup 1.0000x reference)
#include <cuda_runtime.h>
#include <cooperative_groups.h>
namespace cg = cooperative_groups;

#define BB 8
#define CC 64
#define NN 400
#define NN2 (NN * NN)          // 160000
#define NV4 (NN / 4)           // 100
#define TT 16                  // tile dim (400 = 25*16 exact)
#define NT 25                  // tiles per dim
#define NPAIR 300              // off-diagonal unordered pairs r<s
#define NJOBS 313              // 300 pair jobs + 13 diag jobs per batch
#define G 4                    // jobs per cluster (pipeline depth)
#define CPB ((NJOBS + G - 1) / G)   // 79 clusters per batch
#define KT 32                  // k-tile width in epilogue

// Scratch (device globals: no allocation allowed in kernel_launch)
__device__ float g_xp[NT * BB * CC * NN];  // partial x by source n-tile (20.5 MB)
__device__ float g_x [BB * CC * NN];       // reduced x                  (0.82 MB)

struct TileJob { int rt, ct; bool active, partner; };

// Decode job `local` (0..NJOBS-1) for cluster rank; >=NJOBS -> inactive.
// Inactive jobs keep rt=ct=0 so speculative loads stay in-bounds.
__device__ __forceinline__ TileJob decode_job(int local, int rank) {
    TileJob j;
    if (local >= NJOBS) { j.rt = j.ct = 0; j.active = false; j.partner = false; return j; }
    if (local < NPAIR) {
        int r = 0, rem = local;
        while (rem >= (NT - 1) - r) { rem -= (NT - 1) - r; ++r; }
        int s = r + 1 + rem;
        j.rt = rank ? s : r;
        j.ct = rank ? r : s;
        j.active = true; j.partner = true;
    } else {
        int d  = local - NPAIR;
        int dg = 2 * d + rank;
        j.active = (dg < NT);
        j.rt = j.ct = j.active ? dg : 0;
        j.partner = false;
    }
    return j;
}

__device__ __forceinline__ float relutanh(float m) { return (m > 0.f) ? tanhf(m) : 0.f; }

// Combine 4 chain-maxes from cm and publish transposed f-tile into atp_slot
// (partner's for pair jobs, own for diagonal). R12-verified mapping.
__device__ __forceinline__ void publish(const float* cm, float* atp_slot,
                                        const TileJob& j, cg::cluster_group& cl,
                                        int rank, int tid) {
    if (j.active && tid < 64) {
        float4 m0 = *reinterpret_cast<const float4*>(cm + (0 * 64 + tid) * 4);
        float4 m1 = *reinterpret_cast<const float4*>(cm + (1 * 64 + tid) * 4);
        float4 m2 = *reinterpret_cast<const float4*>(cm + (2 * 64 + tid) * 4);
        float4 m3 = *reinterpret_cast<const float4*>(cm + (3 * 64 + tid) * 4);
        float4 m;
        m.x = fmaxf(fmaxf(m0.x, m1.x), fmaxf(m2.x, m3.x));
        m.y = fmaxf(fmaxf(m0.y, m1.y), fmaxf(m2.y, m3.y));
        m.z = fmaxf(fmaxf(m0.z, m1.z), fmaxf(m2.z, m3.z));
        m.w = fmaxf(fmaxf(m0.w, m1.w), fmaxf(m2.w, m3.w));
        int i  = tid >> 2;
        int jq = (tid & 3) * 4;
        float* dst = atp_slot;
        if (j.partner)
            dst = (float*)cl.map_shared_rank((void*)atp_slot, rank ^ 1);
        dst[(jq + 0) * TT + i] = relutanh(m.x);
        dst[(jq + 1) * TT + i] = relutanh(m.y);
        dst[(jq + 2) * TT + i] = relutanh(m.z);
        dst[(jq + 3) * TT + i] = relutanh(m.w);
    }
}

// ---------------------------------------------------------------------------
// kfused7: pipelined cluster kernel. Each 2-CTA cluster processes G jobs.
// Segment 0: DRAM max-loads of job 0. Segments 1..G-1: DRAM max-loads of
// job i INTERLEAVED with L2 acc re-read of job i-1 (both load streams in
// flight -> DRAM and LTS overlap). Final: acc of job G-1. One cl.sync per
// job (same rendezvous rate as R12); reuse gap stays one segment.
// ---------------------------------------------------------------------------
__global__ void __launch_bounds__(256, 6) kfused7(const float* __restrict__ R) {
    __shared__ float cm[4 * 64 * 4];      // per-chain maxes: 4 KB
    __shared__ float atp[G][TT * TT];     // f-tile per pipeline slot: 4 KB

    cg::cluster_group cl = cg::this_cluster();
    const int rank = (int)cl.block_rank();
    const int cid  = (int)blockIdx.x >> 1;
    const int b    = cid / CPB;
    const int j0   = (cid - b * CPB) * G;

    const int tid   = threadIdx.x;
    const int p     = tid & 63;
    const int chain = tid >> 6;           // warp-coherent channel chains
    const int nl    = p >> 2;
    const int k4    = p & 3;
    const int c     = tid >> 2;
    const int kg    = (tid & 3) * 4;

    // ---- segment 0: max-loads of job 0 ----
    {
        TileJob j = decode_job(j0, rank);
        const float* mb = R + (size_t)(b * CC + chain * 16) * NN2
                            + (size_t)(j.rt * TT + nl) * NN + j.ct * TT + k4 * 4;
        float4 mx = *reinterpret_cast<const float4*>(mb);
        #pragma unroll
        for (int q = 1; q < 16; ++q) {
            float4 v = *reinterpret_cast<const float4*>(mb + (size_t)q * NN2);
            mx.x = fmaxf(mx.x, v.x); mx.y = fmaxf(mx.y, v.y);
            mx.z = fmaxf(mx.z, v.z); mx.w = fmaxf(mx.w, v.w);
        }
        *reinterpret_cast<float4*>(cm + (chain * 64 + p) * 4) = mx;
        __syncthreads();
        publish(cm, atp[0], j, cl, rank, tid);
        cl.sync();
    }

    // ---- segments 1..G-1: max(job i) interleaved with acc(job i-1) ----
    #pragma unroll
    for (int i = 1; i < G; ++i) {
        TileJob jm = decode_job(j0 + i, rank);        // DRAM stream
        TileJob ja = decode_job(j0 + i - 1, rank);    // L2 stream

        const float* mb = R + (size_t)(b * CC + chain * 16) * NN2
                            + (size_t)(jm.rt * TT + nl) * NN + jm.ct * TT + k4 * 4;
        const float* ab = R + (size_t)(b * CC + c) * NN2
                            + (size_t)(ja.rt * TT) * NN + ja.ct * TT + kg;
        const float* ap = atp[i - 1];

        float4 mx  = make_float4(-3.4e38f, -3.4e38f, -3.4e38f, -3.4e38f);
        float4 acc = make_float4(0.f, 0.f, 0.f, 0.f);
        #pragma unroll
        for (int q = 0; q < 16; ++q) {
            float4 vm = *reinterpret_cast<const float4*>(mb + (size_t)q * NN2);  // DRAM
            float4 ra = *reinterpret_cast<const float4*>(ab + (size_t)q * NN);   // L2
            float4 av = *reinterpret_cast<const float4*>(ap + q * TT + kg);      // smem
            mx.x = fmaxf(mx.x, vm.x); mx.y = fmaxf(mx.y, vm.y);
            mx.z = fmaxf(mx.z, vm.z); mx.w = fmaxf(mx.w, vm.w);
            acc.x = fmaf(ra.x, av.x, acc.x);
            acc.y = fmaf(ra.y, av.y, acc.y);
            acc.z = fmaf(ra.z, av.z, acc.z);
            acc.w = fmaf(ra.w, av.w, acc.w);
        }
        if (ja.active)
            *reinterpret_cast<float4*>(
                g_xp + (((size_t)ja.rt * BB + b) * CC + c) * NN + ja.ct * TT + kg) = acc;

        *reinterpret_cast<float4*>(cm + (chain * 64 + p) * 4) = mx;
        __syncthreads();
        publish(cm, atp[i], jm, cl, rank, tid);
        cl.sync();
    }

    // ---- final: acc of job G-1 ----
    {
        TileJob j = decode_job(j0 + G - 1, rank);
        const float* ab = R + (size_t)(b * CC + c) * NN2
                            + (size_t)(j.rt * TT) * NN + j.ct * TT + kg;
        const float* ap = atp[G - 1];
        float4 acc = make_float4(0.f, 0.f, 0.f, 0.f);
        #pragma unroll
        for (int q = 0; q < 16; ++q) {
            float4 ra = *reinterpret_cast<const float4*>(ab + (size_t)q * NN);
            float4 av = *reinterpret_cast<const float4*>(ap + q * TT + kg);
            acc.x = fmaf(ra.x, av.x, acc.x);
            acc.y = fmaf(ra.y, av.y, acc.y);
            acc.z = fmaf(ra.z, av.z, acc.z);
            acc.w = fmaf(ra.w, av.w, acc.w);
        }
        if (j.active)
            *reinterpret_cast<float4*>(
                g_xp + (((size_t)j.rt * BB + b) * CC + c) * NN + j.ct * TT + kg) = acc;
    }
}

// ---------------------------------------------------------------------------
// k3a (R9 verbatim): g_x = sum over 25 slots of g_xp.
// ---------------------------------------------------------------------------
__global__ void k3a_reduce() {
    const int total4 = BB * CC * NV4;                  // 51200
    int t = blockIdx.x * blockDim.x + threadIdx.x;
    if (t >= total4) return;
    const float4* xp4 = reinterpret_cast<const float4*>(g_xp);
    const int stride4 = BB * CC * NV4;

    float4 s0 = xp4[t];
    float4 s1 = xp4[(size_t)1 * stride4 + t];
    float4 s2 = xp4[(size_t)2 * stride4 + t];
    float4 s3 = xp4[(size_t)3 * stride4 + t];
    #pragma unroll
    for (int slot = 4; slot + 3 < NT; slot += 4) {
        float4 v0 = xp4[(size_t)(slot + 0) * stride4 + t];
        float4 v1 = xp4[(size_t)(slot + 1) * stride4 + t];
        float4 v2 = xp4[(size_t)(slot + 2) * stride4 + t];
        float4 v3 = xp4[(size_t)(slot + 3) * stride4 + t];
        s0.x += v0.x; s0.y += v0.y; s0.z += v0.z; s0.w += v0.w;
        s1.x += v1.x; s1.y += v1.y; s1.z += v1.z; s1.w += v1.w;
        s2.x += v2.x; s2.y += v2.y; s2.z += v2.z; s2.w += v2.w;
        s3.x += v3.x; s3.y += v3.y; s3.z += v3.z; s3.w += v3.w;
    }
    {
        float4 v = xp4[(size_t)24 * stride4 + t];
        s0.x += v.x; s0.y += v.y; s0.z += v.z; s0.w += v.w;
    }
    float4 s;
    s.x = (s0.x + s1.x) + (s2.x + s3.x);
    s.y = (s0.y + s1.y) + (s2.y + s3.y);
    s.z = (s0.z + s1.z) + (s2.z + s3.z);
    s.w = (s0.w + s1.w) + (s2.w + s3.w);
    reinterpret_cast<float4*>(g_x)[t] = s;
}

// ---------------------------------------------------------------------------
// k3b (R4 verbatim): out[b,o,k] = sum_c W[o,c] * x[b,c,k] + bias[o]
// ---------------------------------------------------------------------------
__global__ void k3b_linear(const float* __restrict__ W,
                           const float* __restrict__ bias,
                           float* __restrict__ out) {
    __shared__ float xs[CC][KT + 1];
    const int b  = blockIdx.z;
    const int og = blockIdx.y;
    const int k0 = blockIdx.x * KT;
    const int x  = threadIdx.x;
    const int y  = threadIdx.y;
    const int k  = k0 + x;
    const bool valid = (k < NN);
    const int kc = valid ? k : (NN - 1);

    for (int c = y; c < CC; c += 8)
        xs[c][x] = g_x[((size_t)b * CC + c) * NN + kc];
    __syncthreads();

    #pragma unroll
    for (int oi = 0; oi < 2; ++oi) {
        int o = og * 16 + y + oi * 8;
        float acc = bias[o];
        const float* wr = W + o * CC;
        #pragma unroll 16
        for (int c = 0; c < CC; ++c)
            acc = fmaf(wr[c], xs[c][x], acc);
        if (valid)
            out[((size_t)b * CC + o) * NN + k] = acc;
    }
}

// ---------------------------------------------------------------------------
extern "C" void kernel_launch(void* const* d_in, const int* in_sizes, int n_in,
                              void* d_out, int out_size) {
    const float* R    = (const float*)d_in[0];
    const float* W    = (const float*)d_in[1];
    const float* bias = (const float*)d_in[2];
    float*       out  = (float*)d_out;

    // Pipelined fused kernel: 8 * 79 clusters * 2 CTAs = 1264 blocks
    {
        cudaLaunchConfig_t cfg = {};
        cfg.gridDim  = dim3(BB * CPB * 2, 1, 1);
        cfg.blockDim = dim3(256, 1, 1);
        cfg.dynamicSmemBytes = 0;
        cfg.stream = 0;
        cudaLaunchAttribute attrs[1];
        attrs[0].id = cudaLaunchAttributeClusterDimension;
        attrs[0].val.clusterDim = {2, 1, 1};
        cfg.attrs = attrs;
        cfg.numAttrs = 1;
        cudaLaunchKernelEx(&cfg, kfused7, R);
    }

    // k3a: 25-slot partial reduce (200 blocks)
    {
        int total4 = BB * CC * NV4;
        k3a_reduce<<<(total4 + 255) / 256, 256>>>();
    }

    // k3b: linear (416 blocks)
    {
        dim3 grid((NN + KT - 1) / KT, 4, BB);
        dim3 blk(32, 8);
        k3b_linear<<<grid, blk>>>(W, bias, out);
    }
}

// round 16
// speedup vs baseline: 1.8515x; 1.8515x over previous
#include <cuda_runtime.h>
#include <cooperative_groups.h>
namespace cg = cooperative_groups;

#define BB 8
#define CC 64
#define NN 400
#define NN2 (NN * NN)          // 160000
#define NV4 (NN / 4)           // 100
#define TT 16                  // tile dim (400 = 25*16 exact)
#define NT 25                  // tiles per dim
#define NPAIR 300              // off-diagonal unordered pairs r<s
#define NDIAGC 13              // diagonal clusters (12 full + 1 half)
#define CLPB (NPAIR + NDIAGC)  // 313 clusters per batch
#define KT 32                  // k-tile width in epilogue

// Scratch (device globals: no allocation allowed in kernel_launch)
__device__ float g_xp[NT * BB * CC * NN];  // partial x by source n-tile (20.5 MB)
__device__ float g_x [BB * CC * NN];       // reduced x                  (0.82 MB)

// ---------------------------------------------------------------------------
// kfused5 (R12 structure, best measured: 82.7us / ~377MB DRAM / total 94.7us).
// Cluster of 2 CTAs = tile pair. Phase 1: stream own 16x16x64ch tile, channel
// max only; publish transposed f-tile DIRECTLY into partner's atp via DSMEM.
// Single cluster.sync. Phase 2: re-read own tile (L2-hot) and accumulate.
// ONLY change vs R12: full unroll (16) of the phase-2 loop for deeper MLP in
// the L2-latency-dominated phase. 6 CTAs/SM (R13: 8 breaks L2 residency).
// ---------------------------------------------------------------------------
__global__ void __launch_bounds__(256, 6) kfused5(const float* __restrict__ R) {
    __shared__ float cm[4 * 64 * 4];      // per-chain maxes (float4 each): 4 KB
    __shared__ float atp[TT * TT];        // f-tile of PARTNER's R-tile:   1 KB

    cg::cluster_group cl = cg::this_cluster();
    const int rank  = (int)cl.block_rank();
    const int cid   = (int)blockIdx.x >> 1;
    const int b     = cid / CLPB;
    const int local = cid - b * CLPB;

    int rt, ct;
    bool active = true;
    bool have_partner;
    if (local < NPAIR) {
        int r = 0, rem = local;
        while (rem >= (NT - 1) - r) { rem -= (NT - 1) - r; ++r; }
        int s = r + 1 + rem;
        rt = rank ? s : r;
        ct = rank ? r : s;
        have_partner = true;
    } else {
        int d  = local - NPAIR;
        int dg = 2 * d + rank;
        active = (dg < NT);
        rt = ct = active ? dg : 0;
        have_partner = false;
    }

    const int tid   = threadIdx.x;        // 256
    const int p     = tid & 63;
    const int chain = tid >> 6;           // 0..3 -> channels chain*16..+15 (warp-coherent)
    const int nl    = p >> 2;             // local row 0..15
    const int k4    = p & 3;              // k quad 0..3

    // ---- Phase 1: channel max over my 16 channels at (nl, k4*4..+3) ----
    if (active) {
        const float* base = R + (size_t)(b * CC + chain * 16) * NN2
                              + (size_t)(rt * TT + nl) * NN + ct * TT + k4 * 4;
        float4 mx = *reinterpret_cast<const float4*>(base);
        #pragma unroll
        for (int ci = 1; ci < 16; ++ci) {
            float4 v = *reinterpret_cast<const float4*>(base + (size_t)ci * NN2);
            mx.x = fmaxf(mx.x, v.x); mx.y = fmaxf(mx.y, v.y);
            mx.z = fmaxf(mx.z, v.z); mx.w = fmaxf(mx.w, v.w);
        }
        *reinterpret_cast<float4*>(cm + (chain * 64 + p) * 4) = mx;
    }
    __syncthreads();

    // ---- combine 4 chains, relu(tanh), write TRANSPOSED f-tile directly
    //      into the PARTNER's atp (remote DSMEM store; local for diagonal) ----
    if (active && tid < 64) {
        float4 m0 = *reinterpret_cast<float4*>(cm + (0 * 64 + tid) * 4);
        float4 m1 = *reinterpret_cast<float4*>(cm + (1 * 64 + tid) * 4);
        float4 m2 = *reinterpret_cast<float4*>(cm + (2 * 64 + tid) * 4);
        float4 m3 = *reinterpret_cast<float4*>(cm + (3 * 64 + tid) * 4);
        float4 m;
        m.x = fmaxf(fmaxf(m0.x, m1.x), fmaxf(m2.x, m3.x));
        m.y = fmaxf(fmaxf(m0.y, m1.y), fmaxf(m2.y, m3.y));
        m.z = fmaxf(fmaxf(m0.z, m1.z), fmaxf(m2.z, m3.z));
        m.w = fmaxf(fmaxf(m0.w, m1.w), fmaxf(m2.w, m3.w));
        int i  = tid >> 2;                // local row of MY tile
        int jq = (tid & 3) * 4;           // local col quad of MY tile
        float* dst = atp;
        if (have_partner)
            dst = (float*)cl.map_shared_rank((void*)atp, rank ^ 1);
        dst[(jq + 0) * TT + i] = (m.x > 0.f) ? tanhf(m.x) : 0.f;
        dst[(jq + 1) * TT + i] = (m.y > 0.f) ? tanhf(m.y) : 0.f;
        dst[(jq + 2) * TT + i] = (m.z > 0.f) ? tanhf(m.z) : 0.f;
        dst[(jq + 3) * TT + i] = (m.w > 0.f) ? tanhf(m.w) : 0.f;
    }

    // ---- single rendezvous ----
    cl.sync();

    // ---- Phase 2: re-read own tile (L2-hot), accumulate (FULL unroll) ----
    // atp[n][k_local] = A[b, ct*16+k, rt*16+n]  (written by partner)
    if (active) {
        const int c  = tid >> 2;          // 0..63
        const int kg = (tid & 3) * 4;     // k quad base
        const float* rb = R + (size_t)(b * CC + c) * NN2
                            + (size_t)(rt * TT) * NN + ct * TT + kg;
        float4 acc = make_float4(0.f, 0.f, 0.f, 0.f);
        #pragma unroll
        for (int n = 0; n < TT; ++n) {
            float4 r = *reinterpret_cast<const float4*>(rb + (size_t)n * NN);
            float4 a = *reinterpret_cast<const float4*>(atp + n * TT + kg);
            acc.x = fmaf(r.x, a.x, acc.x);
            acc.y = fmaf(r.y, a.y, acc.y);
            acc.z = fmaf(r.z, a.z, acc.z);
            acc.w = fmaf(r.w, a.w, acc.w);
        }
        *reinterpret_cast<float4*>(
            g_xp + (((size_t)rt * BB + b) * CC + c) * NN + ct * TT + kg) = acc;
    }
}

// ---------------------------------------------------------------------------
// k3a (R9 verbatim): g_x = sum over 25 slots of g_xp.
// ---------------------------------------------------------------------------
__global__ void k3a_reduce() {
    const int total4 = BB * CC * NV4;                  // 51200
    int t = blockIdx.x * blockDim.x + threadIdx.x;
    if (t >= total4) return;
    const float4* xp4 = reinterpret_cast<const float4*>(g_xp);
    const int stride4 = BB * CC * NV4;

    float4 s0 = xp4[t];
    float4 s1 = xp4[(size_t)1 * stride4 + t];
    float4 s2 = xp4[(size_t)2 * stride4 + t];
    float4 s3 = xp4[(size_t)3 * stride4 + t];
    #pragma unroll
    for (int slot = 4; slot + 3 < NT; slot += 4) {
        float4 v0 = xp4[(size_t)(slot + 0) * stride4 + t];
        float4 v1 = xp4[(size_t)(slot + 1) * stride4 + t];
        float4 v2 = xp4[(size_t)(slot + 2) * stride4 + t];
        float4 v3 = xp4[(size_t)(slot + 3) * stride4 + t];
        s0.x += v0.x; s0.y += v0.y; s0.z += v0.z; s0.w += v0.w;
        s1.x += v1.x; s1.y += v1.y; s1.z += v1.z; s1.w += v1.w;
        s2.x += v2.x; s2.y += v2.y; s2.z += v2.z; s2.w += v2.w;
        s3.x += v3.x; s3.y += v3.y; s3.z += v3.z; s3.w += v3.w;
    }
    {
        float4 v = xp4[(size_t)24 * stride4 + t];
        s0.x += v.x; s0.y += v.y; s0.z += v.z; s0.w += v.w;
    }
    float4 s;
    s.x = (s0.x + s1.x) + (s2.x + s3.x);
    s.y = (s0.y + s1.y) + (s2.y + s3.y);
    s.z = (s0.z + s1.z) + (s2.z + s3.z);
    s.w = (s0.w + s1.w) + (s2.w + s3.w);
    reinterpret_cast<float4*>(g_x)[t] = s;
}

// ---------------------------------------------------------------------------
// k3b (R4 verbatim): out[b,o,k] = sum_c W[o,c] * x[b,c,k] + bias[o]
// ---------------------------------------------------------------------------
__global__ void k3b_linear(const float* __restrict__ W,
                           const float* __restrict__ bias,
                           float* __restrict__ out) {
    __shared__ float xs[CC][KT + 1];
    const int b  = blockIdx.z;
    const int og = blockIdx.y;
    const int k0 = blockIdx.x * KT;
    const int x  = threadIdx.x;
    const int y  = threadIdx.y;
    const int k  = k0 + x;
    const bool valid = (k < NN);
    const int kc = valid ? k : (NN - 1);

    for (int c = y; c < CC; c += 8)
        xs[c][x] = g_x[((size_t)b * CC + c) * NN + kc];
    __syncthreads();

    #pragma unroll
    for (int oi = 0; oi < 2; ++oi) {
        int o = og * 16 + y + oi * 8;
        float acc = bias[o];
        const float* wr = W + o * CC;
        #pragma unroll 16
        for (int c = 0; c < CC; ++c)
            acc = fmaf(wr[c], xs[c][x], acc);
        if (valid)
            out[((size_t)b * CC + o) * NN + k] = acc;
    }
}

// ---------------------------------------------------------------------------
extern "C" void kernel_launch(void* const* d_in, const int* in_sizes, int n_in,
                              void* d_out, int out_size) {
    const float* R    = (const float*)d_in[0];
    const float* W    = (const float*)d_in[1];
    const float* bias = (const float*)d_in[2];
    float*       out  = (float*)d_out;

    // Fused single-read kernel: 8 * 313 clusters * 2 CTAs = 5008 blocks
    {
        cudaLaunchConfig_t cfg = {};
        cfg.gridDim  = dim3(BB * CLPB * 2, 1, 1);
        cfg.blockDim = dim3(256, 1, 1);
        cfg.dynamicSmemBytes = 0;
        cfg.stream = 0;
        cudaLaunchAttribute attrs[1];
        attrs[0].id = cudaLaunchAttributeClusterDimension;
        attrs[0].val.clusterDim = {2, 1, 1};
        cfg.attrs = attrs;
        cfg.numAttrs = 1;
        cudaLaunchKernelEx(&cfg, kfused5, R);
    }

    // k3a: 25-slot partial reduce (200 blocks)
    {
        int total4 = BB * CC * NV4;
        k3a_reduce<<<(total4 + 255) / 256, 256>>>();
    }

    // k3b: linear (416 blocks)
    {
        dim3 grid((NN + KT - 1) / KT, 4, BB);
        dim3 blk(32, 8);
        k3b_linear<<<grid, blk>>>(W, bias, out);
    }
}

// round 17
// speedup vs baseline: 1.8935x; 1.0227x over previous
#include <cuda_runtime.h>
#include <cooperative_groups.h>
namespace cg = cooperative_groups;

#define BB 8
#define CC 64
#define NN 400
#define NN2 (NN * NN)          // 160000
#define NV4 (NN / 4)           // 100 float4 per row
#define TT 16                  // tile dim (400 = 25*16 exact)
#define NT 25                  // tiles per dim
#define NPAIR 300              // off-diagonal unordered pairs r<s
#define NDIAGC 13              // diagonal clusters (12 full + 1 half)
#define CLPB (NPAIR + NDIAGC)  // 313 clusters per batch
#define QC 4                   // k-quads per epilogue block (16 k)
#define NCHK (NV4 / QC)        // 25 quad-chunks

// Scratch (device globals: no allocation allowed in kernel_launch)
__device__ float g_xp[NT * BB * CC * NN];  // partial x by source n-tile (20.5 MB)

// ---------------------------------------------------------------------------
// kfused5 (R16 verbatim — best measured: 78.75us, ~386MB DRAM).
// Cluster of 2 CTAs = tile pair. Phase 1: stream own 16x16x64ch tile, channel
// max only; publish transposed f-tile DIRECTLY into partner's atp via DSMEM.
// Single cluster.sync. Phase 2: re-read own tile (L2-hot), full-unroll
// accumulate. 6 CTAs/SM (R13: 8 breaks L2 residency).
// ---------------------------------------------------------------------------
__global__ void __launch_bounds__(256, 6) kfused5(const float* __restrict__ R) {
    __shared__ float cm[4 * 64 * 4];      // per-chain maxes (float4 each): 4 KB
    __shared__ float atp[TT * TT];        // f-tile of PARTNER's R-tile:   1 KB

    cg::cluster_group cl = cg::this_cluster();
    const int rank  = (int)cl.block_rank();
    const int cid   = (int)blockIdx.x >> 1;
    const int b     = cid / CLPB;
    const int local = cid - b * CLPB;

    int rt, ct;
    bool active = true;
    bool have_partner;
    if (local < NPAIR) {
        int r = 0, rem = local;
        while (rem >= (NT - 1) - r) { rem -= (NT - 1) - r; ++r; }
        int s = r + 1 + rem;
        rt = rank ? s : r;
        ct = rank ? r : s;
        have_partner = true;
    } else {
        int d  = local - NPAIR;
        int dg = 2 * d + rank;
        active = (dg < NT);
        rt = ct = active ? dg : 0;
        have_partner = false;
    }

    const int tid   = threadIdx.x;        // 256
    const int p     = tid & 63;
    const int chain = tid >> 6;           // 0..3 -> channels chain*16..+15 (warp-coherent)
    const int nl    = p >> 2;             // local row 0..15
    const int k4    = p & 3;              // k quad 0..3

    // ---- Phase 1: channel max over my 16 channels at (nl, k4*4..+3) ----
    if (active) {
        const float* base = R + (size_t)(b * CC + chain * 16) * NN2
                              + (size_t)(rt * TT + nl) * NN + ct * TT + k4 * 4;
        float4 mx = *reinterpret_cast<const float4*>(base);
        #pragma unroll
        for (int ci = 1; ci < 16; ++ci) {
            float4 v = *reinterpret_cast<const float4*>(base + (size_t)ci * NN2);
            mx.x = fmaxf(mx.x, v.x); mx.y = fmaxf(mx.y, v.y);
            mx.z = fmaxf(mx.z, v.z); mx.w = fmaxf(mx.w, v.w);
        }
        *reinterpret_cast<float4*>(cm + (chain * 64 + p) * 4) = mx;
    }
    __syncthreads();

    // ---- combine 4 chains, relu(tanh), write TRANSPOSED f-tile directly
    //      into the PARTNER's atp (remote DSMEM store; local for diagonal) ----
    if (active && tid < 64) {
        float4 m0 = *reinterpret_cast<float4*>(cm + (0 * 64 + tid) * 4);
        float4 m1 = *reinterpret_cast<float4*>(cm + (1 * 64 + tid) * 4);
        float4 m2 = *reinterpret_cast<float4*>(cm + (2 * 64 + tid) * 4);
        float4 m3 = *reinterpret_cast<float4*>(cm + (3 * 64 + tid) * 4);
        float4 m;
        m.x = fmaxf(fmaxf(m0.x, m1.x), fmaxf(m2.x, m3.x));
        m.y = fmaxf(fmaxf(m0.y, m1.y), fmaxf(m2.y, m3.y));
        m.z = fmaxf(fmaxf(m0.z, m1.z), fmaxf(m2.z, m3.z));
        m.w = fmaxf(fmaxf(m0.w, m1.w), fmaxf(m2.w, m3.w));
        int i  = tid >> 2;                // local row of MY tile
        int jq = (tid & 3) * 4;           // local col quad of MY tile
        float* dst = atp;
        if (have_partner)
            dst = (float*)cl.map_shared_rank((void*)atp, rank ^ 1);
        dst[(jq + 0) * TT + i] = (m.x > 0.f) ? tanhf(m.x) : 0.f;
        dst[(jq + 1) * TT + i] = (m.y > 0.f) ? tanhf(m.y) : 0.f;
        dst[(jq + 2) * TT + i] = (m.z > 0.f) ? tanhf(m.z) : 0.f;
        dst[(jq + 3) * TT + i] = (m.w > 0.f) ? tanhf(m.w) : 0.f;
    }

    // ---- single rendezvous ----
    cl.sync();

    // ---- Phase 2: re-read own tile (L2-hot), accumulate (full unroll) ----
    // atp[n][k_local] = A[b, ct*16+k, rt*16+n]  (written by partner)
    if (active) {
        const int c  = tid >> 2;          // 0..63
        const int kg = (tid & 3) * 4;     // k quad base
        const float* rb = R + (size_t)(b * CC + c) * NN2
                            + (size_t)(rt * TT) * NN + ct * TT + kg;
        float4 acc = make_float4(0.f, 0.f, 0.f, 0.f);
        #pragma unroll
        for (int n = 0; n < TT; ++n) {
            float4 r = *reinterpret_cast<const float4*>(rb + (size_t)n * NN);
            float4 a = *reinterpret_cast<const float4*>(atp + n * TT + kg);
            acc.x = fmaf(r.x, a.x, acc.x);
            acc.y = fmaf(r.y, a.y, acc.y);
            acc.z = fmaf(r.z, a.z, acc.z);
            acc.w = fmaf(r.w, a.w, acc.w);
        }
        *reinterpret_cast<float4*>(
            g_xp + (((size_t)rt * BB + b) * CC + c) * NN + ct * TT + kg) = acc;
    }
}

// ---------------------------------------------------------------------------
// k3f2: fused epilogue with k3a's PROVEN access pattern.
//   Stage 1 (per thread, c = tid>>2, q = tid&3): reduce its float4 quad over
//   all 25 xp slots — 25 independent float4 loads (MLP-25, 4 acc chains),
//   exactly k3a's shape — into smem xs[c][q].
//   Stage 2 (thread -> o = tid>>2, q = tid&3): 64-c dot with W row + bias,
//   write out quad. Eliminates the g_x round-trip and one launch.
// Grid (25 quad-chunks, 8 b) = 200 blocks x 256.
// ---------------------------------------------------------------------------
__global__ void k3f2_epilogue(const float* __restrict__ W,
                              const float* __restrict__ bias,
                              float* __restrict__ out) {
    __shared__ float4 xs[CC][QC];         // 64 x 4 float4 = 4 KB
    const int b     = blockIdx.y;
    const int chunk = blockIdx.x;         // 0..24
    const int tid   = threadIdx.x;
    const int c     = tid >> 2;           // stage-1 channel / stage-2 out-channel
    const int q     = tid & 3;            // quad within chunk
    const int quad  = chunk * QC + q;     // global float4 index, < NV4

    // Stage 1: 25-slot reduce (4 independent chains, all loads independent)
    {
        const float4* xp4 = reinterpret_cast<const float4*>(g_xp);
        const size_t  base    = ((size_t)b * CC + c) * NV4 + quad;
        const size_t  stride4 = (size_t)BB * CC * NV4;

        float4 s0 = xp4[base];
        float4 s1 = xp4[stride4 * 1 + base];
        float4 s2 = xp4[stride4 * 2 + base];
        float4 s3 = xp4[stride4 * 3 + base];
        #pragma unroll
        for (int slot = 4; slot + 3 < NT; slot += 4) {
            float4 v0 = xp4[stride4 * (slot + 0) + base];
            float4 v1 = xp4[stride4 * (slot + 1) + base];
            float4 v2 = xp4[stride4 * (slot + 2) + base];
            float4 v3 = xp4[stride4 * (slot + 3) + base];
            s0.x += v0.x; s0.y += v0.y; s0.z += v0.z; s0.w += v0.w;
            s1.x += v1.x; s1.y += v1.y; s1.z += v1.z; s1.w += v1.w;
            s2.x += v2.x; s2.y += v2.y; s2.z += v2.z; s2.w += v2.w;
            s3.x += v3.x; s3.y += v3.y; s3.z += v3.z; s3.w += v3.w;
        }
        {
            float4 v = xp4[stride4 * 24 + base];
            s0.x += v.x; s0.y += v.y; s0.z += v.z; s0.w += v.w;
        }
        float4 s;
        s.x = (s0.x + s1.x) + (s2.x + s3.x);
        s.y = (s0.y + s1.y) + (s2.y + s3.y);
        s.z = (s0.z + s1.z) + (s2.z + s3.z);
        s.w = (s0.w + s1.w) + (s2.w + s3.w);
        xs[c][q] = s;
    }
    __syncthreads();

    // Stage 2: linear. o = c mapping reuse; smem reads broadcast within warp.
    {
        const int o = c;
        const float bo = bias[o];
        const float* wr = W + o * CC;
        float4 acc = make_float4(bo, bo, bo, bo);
        #pragma unroll 16
        for (int ci = 0; ci < CC; ++ci) {
            float w = wr[ci];
            float4 xv = xs[ci][q];
            acc.x = fmaf(w, xv.x, acc.x);
            acc.y = fmaf(w, xv.y, acc.y);
            acc.z = fmaf(w, xv.z, acc.z);
            acc.w = fmaf(w, xv.w, acc.w);
        }
        reinterpret_cast<float4*>(out)[((size_t)b * CC + o) * NV4 + quad] = acc;
    }
}

// ---------------------------------------------------------------------------
extern "C" void kernel_launch(void* const* d_in, const int* in_sizes, int n_in,
                              void* d_out, int out_size) {
    const float* R    = (const float*)d_in[0];
    const float* W    = (const float*)d_in[1];
    const float* bias = (const float*)d_in[2];
    float*       out  = (float*)d_out;

    // Fused single-read kernel: 8 * 313 clusters * 2 CTAs = 5008 blocks
    {
        cudaLaunchConfig_t cfg = {};
        cfg.gridDim  = dim3(BB * CLPB * 2, 1, 1);
        cfg.blockDim = dim3(256, 1, 1);
        cfg.dynamicSmemBytes = 0;
        cfg.stream = 0;
        cudaLaunchAttribute attrs[1];
        attrs[0].id = cudaLaunchAttributeClusterDimension;
        attrs[0].val.clusterDim = {2, 1, 1};
        cfg.attrs = attrs;
        cfg.numAttrs = 1;
        cudaLaunchKernelEx(&cfg, kfused5, R);
    }

    // Fused epilogue: (25 chunks x 8 b) = 200 blocks
    {
        dim3 grid(NCHK, BB);
        k3f2_epilogue<<<grid, 256>>>(W, bias, out);
    }
}